// round 1
// baseline (speedup 1.0000x reference)
#include <cuda_runtime.h>
#include <math.h>

#define NH 8
#define SEQ 32
#define DK 8
#define DM 64
#define PI_F 3.14159265358979323846f
#define W_MUL 0.6324555320336759f  // sqrt(2)/sqrt(5)

static __device__ float g_z[NH * SEQ * DK];

__device__ __forceinline__ float2 cmul(float2 a, float2 b) {
    return make_float2(fmaf(a.x, b.x, -a.y * b.y), fmaf(a.x, b.y, a.y * b.x));
}
// a * conj(b)
__device__ __forceinline__ float2 cmulc(float2 a, float2 b) {
    return make_float2(fmaf(a.x, b.x, a.y * b.y), fmaf(a.y, b.x, -a.x * b.y));
}
__device__ __forceinline__ float2 cadd(float2 a, float2 b) {
    return make_float2(a.x + b.x, a.y + b.y);
}

// CNOT-ring basis permutation f(j): apply CNOT(c=t, t=(t+1)%6) for t=0..5
__device__ __forceinline__ int permf(int x) {
#pragma unroll
    for (int t = 0; t < 6; t++) {
        int cb = 5 - t;
        int tb = 5 - ((t + 1) % 6);
        if ((x >> cb) & 1) x ^= (1 << tb);
    }
    return x;
}

__global__ void __launch_bounds__(64, 8)
qattn_main(const float* __restrict__ x,     // (32,64)
           const float* __restrict__ pqc,   // (8,3,9)
           const float* __restrict__ W1,    // (8,64)
           const float* __restrict__ b1)    // (8,)
{
    const int h = blockIdx.x >> 5;
    const int i = blockIdx.x & 31;
    const int t = threadIdx.x;      // 0..63
    const int a = t >> 3;
    const int c = t & 7;

    __shared__ float  s_xq[SEQ][DK];
    __shared__ float  s_psi[SEQ][DK];
    __shared__ float2 s_u[3][3][4];       // [g][qubit][2x2]
    __shared__ float  s_qd[DK];
    __shared__ float  s_kd[SEQ][DK];
    __shared__ float2 s_phiv[SEQ][DK];
    __shared__ float  s_phi[SEQ];
    __shared__ float  s_ms[64];
    __shared__ int    s_finv[64];
    __shared__ float2 s_rho[2][64];
    __shared__ float2 s_term[64];
    __shared__ float2 s_chi[8];

    // ---- Phase 1: permutation tables ----
    {
        int y = permf(t);
        s_finv[y] = t;                       // finv = f^{-1}
        s_ms[t] = (__popc(y) & 1) ? -1.0f : 1.0f;
    }

    // ---- Phase 2: xq = x @ W1^T + b1 ; psi = normalize(xq) ----
    for (int idx = t; idx < SEQ * DK; idx += 64) {
        int s = idx >> 3, cc = idx & 7;
        float acc = b1[cc];
        const float* xr = x + s * DM;
        const float* wr = W1 + cc * DM;
#pragma unroll 8
        for (int d = 0; d < DM; d++) acc = fmaf(xr[d], wr[d], acc);
        s_xq[s][cc] = acc;
    }
    __syncthreads();
    for (int idx = t; idx < SEQ * DK; idx += 64) {
        int s = idx >> 3, cc = idx & 7;
        float n = 0.f;
#pragma unroll
        for (int e = 0; e < DK; e++) n = fmaf(s_xq[s][e], s_xq[s][e], n);
        s_psi[s][cc] = s_xq[s][cc] * rsqrtf(n);
    }

    // ---- Phase 3: per-qubit 2x2 unitaries u = Rz(a2) Ry(a1) Rx(a0) ----
    if (t < 9) {
        int g = t / 3, q = t % 3;
        const float* ap = pqc + h * 27 + g * 9 + q * 3;
        float a0 = ap[0] * W_MUL, a1 = ap[1] * W_MUL, a2 = ap[2] * W_MUL;
        float sx, cx, sy, cy, sz, cz;
        sincosf(0.5f * a0, &sx, &cx);
        sincosf(0.5f * a1, &sy, &cy);
        sincosf(0.5f * a2, &sz, &cz);
        // Ry*Rx
        float2 m00 = make_float2(cy * cx,  sy * sx);
        float2 m01 = make_float2(-sy * cx, -cy * sx);
        float2 m10 = make_float2(sy * cx,  -cy * sx);
        float2 m11 = make_float2(cy * cx,  -sy * sx);
        float2 e0 = make_float2(cz, -sz);
        float2 e1 = make_float2(cz,  sz);
        s_u[g][q][0] = cmul(e0, m00);
        s_u[g][q][1] = cmul(e0, m01);
        s_u[g][q][2] = cmul(e1, m10);
        s_u[g][q][3] = cmul(e1, m11);
    }
    __syncthreads();

    // ---- Phase 4: phi_g[s] = U[h,g] psi_s ; qdiag/kdiag = |.|^2, phiv stored ----
    for (int idx = t; idx < 96; idx += 64) {
        int g = idx >> 5, s = idx & 31;
        float2 v[8];
#pragma unroll
        for (int e = 0; e < 8; e++) v[e] = make_float2(s_psi[s][e], 0.f);
#pragma unroll
        for (int q = 0; q < 3; q++) {
            int p = 2 - q;  // qubit 0 = MSB
            float2 u0 = s_u[g][q][0], u1 = s_u[g][q][1];
            float2 u2 = s_u[g][q][2], u3 = s_u[g][q][3];
#pragma unroll
            for (int k = 0; k < 8; k++) {
                if ((k >> p) & 1) continue;
                int k1 = k | (1 << p);
                float2 v0 = v[k], v1 = v[k1];
                v[k]  = cadd(cmul(u0, v0), cmul(u1, v1));
                v[k1] = cadd(cmul(u2, v0), cmul(u3, v1));
            }
        }
        if (g == 0) {
            if (s == i) {
#pragma unroll
                for (int e = 0; e < 8; e++)
                    s_qd[e] = fmaf(v[e].x, v[e].x, v[e].y * v[e].y);
            }
        } else if (g == 1) {
#pragma unroll
            for (int e = 0; e < 8; e++)
                s_kd[s][e] = fmaf(v[e].x, v[e].x, v[e].y * v[e].y);
        } else {
#pragma unroll
            for (int e = 0; e < 8; e++) s_phiv[s][e] = v[e];
        }
    }
    __syncthreads();

    // ---- Phase 5: phi[j] = pi * sum_{c,d} m[8c+d] qd[c] kd[j][d] ----
    if (t < SEQ) {
        float acc = 0.f;
#pragma unroll
        for (int cc = 0; cc < 8; cc++) {
            float qv = s_qd[cc];
#pragma unroll
            for (int d = 0; d < 8; d++)
                acc = fmaf(s_ms[cc * 8 + d] * qv, s_kd[t][d], acc);
        }
        s_phi[t] = acc * PI_F;
    }
    __syncthreads();

    // per-thread gather indices for the scan contraction
    int pa[8], qa[8];
#pragma unroll
    for (int b = 0; b < 8; b++) {
        pa[b] = s_finv[a * 8 + b];
        qa[b] = s_finv[c * 8 + b];
    }

    // ---- Phase 6: sequential scan over j = 0..31 ----
    int cur = 0;
    for (int j = 0; j < SEQ; j++) {
        float ph = s_phi[j];
        float s4, c4, sh, ch;
        sincosf(0.25f * ph, &s4, &c4);
        sincosf(0.50f * ph, &sh, &ch);
        float cc2 = c4 * c4, ss2 = s4 * s4, cs2 = c4 * s4;
        float2 e0 = make_float2(ch, -sh);
        float2 e1 = make_float2(ch,  sh);
        float2 u00 = cmul(e0, make_float2(cc2,  ss2));
        float2 u01 = cmul(e0, make_float2(-cs2, -cs2));
        float2 u10 = cmul(e1, make_float2(cs2,  -cs2));
        float2 u11 = cmul(e1, make_float2(cc2,  -ss2));

        // term[r,c] = Uw[r,c] * phiv[j][c]  (Uw = u (x) u (x) u)
        {
            int r = a, cl = c;
            float2 f2 = ((r >> 2) & 1) ? (((cl >> 2) & 1) ? u11 : u10)
                                       : (((cl >> 2) & 1) ? u01 : u00);
            float2 f1 = ((r >> 1) & 1) ? (((cl >> 1) & 1) ? u11 : u10)
                                       : (((cl >> 1) & 1) ? u01 : u00);
            float2 f0 = (r & 1) ? ((cl & 1) ? u11 : u10)
                                : ((cl & 1) ? u01 : u00);
            s_term[t] = cmul(cmul(cmul(f2, f1), f0), s_phiv[j][cl]);
        }
        __syncthreads();
        if (t < 8) {
            float2 acc = make_float2(0.f, 0.f);
#pragma unroll
            for (int e = 0; e < 8; e++) acc = cadd(acc, s_term[t * 8 + e]);
            s_chi[t] = acc;
        }
        __syncthreads();

        float2 nr;
        if (j == 0) {
            nr = cmulc(s_chi[a], s_chi[c]);  // chi chi^dagger
        } else {
            float2 acc = make_float2(0.f, 0.f);
            const float2* rho = s_rho[cur];
#pragma unroll
            for (int b = 0; b < 8; b++) {
                int p = pa[b], q = qa[b];
                float2 rr = rho[(p >> 3) * 8 + (q >> 3)];
                float2 wk = cmulc(s_chi[p & 7], s_chi[q & 7]);
                acc = cadd(acc, cmul(rr, wk));
            }
            nr = acc;
        }
        s_rho[cur ^ 1][t] = nr;
        cur ^= 1;
        __syncthreads();
    }

    if (a == c) g_z[h * (SEQ * DK) + i * DK + a] = s_rho[cur][t].x;
}

__global__ void __launch_bounds__(64)
qattn_out(const float* __restrict__ W2,   // (64,64)
          const float* __restrict__ b2,   // (64,)
          float* __restrict__ out)        // (1,32,64)
{
    int s = blockIdx.x;    // 0..31
    int d = threadIdx.x;   // 0..63
    float acc = b2[d];
    const float* wr = W2 + d * DM;
#pragma unroll 8
    for (int e = 0; e < DM; e++) {
        float z = g_z[(e >> 3) * (SEQ * DK) + s * DK + (e & 7)];
        acc = fmaf(z, wr[e], acc);
    }
    out[s * DM + d] = acc;
}

extern "C" void kernel_launch(void* const* d_in, const int* in_sizes, int n_in,
                              void* d_out, int out_size) {
    const float* x    = (const float*)d_in[0];
    const float* pqc  = (const float*)d_in[1];
    const float* W1   = (const float*)d_in[2];
    const float* b1   = (const float*)d_in[3];
    const float* W2   = (const float*)d_in[4];
    const float* b2   = (const float*)d_in[5];
    float* out = (float*)d_out;

    qattn_main<<<NH * SEQ, 64>>>(x, pqc, W1, b1);
    qattn_out<<<SEQ, 64>>>(W2, b2, out);
}